// round 13
// baseline (speedup 1.0000x reference)
#include <cuda_runtime.h>
#include <cstdint>

#define NN 100000
#define MAXE 1600000
#define FEAT 128
#define NB_MAX ((NN + 1023) / 1024)

typedef unsigned long long u64;

// ---------------- device scratch (no allocs allowed) ----------------
__device__ float g_msg[(size_t)NN * FEAT];
__device__ float g_h[(size_t)NN * FEAT];
__device__ int   g_cnt[NN];      // degree per node
__device__ int   g_cnt2[NN];     // fill cursor (scan writes exclusive prefix)
__device__ int   g_scanTmp[NN];  // inclusive prefix of cnt
__device__ int   g_col[MAXE];
__device__ u64   g_tile[NB_MAX]; // lookback tile state: flag<<32 | value
__device__ int   g_ctr[4];       // GEMM tile counters per layer

#define FLAG_PARTIAL 1ULL
#define FLAG_INCL    2ULL

// ================= zero =================
__global__ void zero_kernel(int n, int nb) {
    int i = blockIdx.x * blockDim.x + threadIdx.x;
    if (i < n) g_cnt[i] = 0;
    if (i < nb) g_tile[i] = 0;
    if (i < 4) g_ctr[i] = 0;
}

// ================= histogram (4 edges/thread, vectorized) =================
__global__ void hist_kernel(const int* __restrict__ dst, int nE) {
    int q = blockIdx.x * blockDim.x + threadIdx.x;   // quad index
    int base = q * 4;
    if (base + 4 <= nE) {
        int4 d = __ldg((const int4*)(dst + base));
        atomicAdd(&g_cnt[d.x], 1);
        atomicAdd(&g_cnt[d.y], 1);
        atomicAdd(&g_cnt[d.z], 1);
        atomicAdd(&g_cnt[d.w], 1);
    } else if (base < nE) {
        for (int i = base; i < nE; i++)
            atomicAdd(&g_cnt[__ldg(dst + i)], 1);
    }
}

// ================= single-pass scan (decoupled lookback) =================
// writes inclusive prefix to g_scanTmp AND exclusive prefix to g_cnt2 (fill cursor)
__global__ __launch_bounds__(1024)
void scan_kernel(int n) {
    __shared__ int sh[1024];
    __shared__ int s_prefix;
    const int b = blockIdx.x;
    const int t = threadIdx.x;
    const int i = b * 1024 + t;

    int v = (i < n) ? g_cnt[i] : 0;
    sh[t] = v;
    __syncthreads();
#pragma unroll
    for (int off = 1; off < 1024; off <<= 1) {
        int tv = (t >= off) ? sh[t - off] : 0;
        __syncthreads();
        sh[t] += tv;
        __syncthreads();
    }
    int total = sh[1023];

    if (b == 0) {
        if (t == 0) {
            s_prefix = 0;
            atomicExch(&g_tile[0], (FLAG_INCL << 32) | (unsigned)total);
        }
    } else {
        if (t == 0)
            atomicExch(&g_tile[b], (FLAG_PARTIAL << 32) | (unsigned)total);
        if (t < 32) {
            int lane = t;
            int offset = b - 1;
            int prefix = 0;
            for (;;) {
                int idx = offset - lane;
                u64 st = (idx >= 0) ? atomicAdd(&g_tile[idx], 0ULL)
                                    : (FLAG_INCL << 32);
                unsigned rdy = __ballot_sync(0xffffffffu, (st >> 32) != 0);
                if (rdy != 0xffffffffu) continue;
                unsigned inclm = __ballot_sync(0xffffffffu, (st >> 32) == FLAG_INCL);
                int val = (int)(unsigned)st;
                if (inclm) {
                    int L = __ffs(inclm) - 1;
                    int c = (lane <= L) ? val : 0;
#pragma unroll
                    for (int o = 16; o; o >>= 1) c += __shfl_xor_sync(0xffffffffu, c, o);
                    prefix += c;
                    break;
                } else {
                    int c = val;
#pragma unroll
                    for (int o = 16; o; o >>= 1) c += __shfl_xor_sync(0xffffffffu, c, o);
                    prefix += c;
                    offset -= 32;
                }
            }
            if (lane == 0) {
                s_prefix = prefix;
                atomicExch(&g_tile[b], (FLAG_INCL << 32) | (unsigned)(prefix + total));
            }
        }
    }
    __syncthreads();
    if (i < n) {
        int incl = sh[t] + s_prefix;
        g_scanTmp[i] = incl;
        g_cnt2[i]    = incl - v;   // exclusive prefix = fill cursor base
    }
}

// ================= fill CSR columns (4 edges/thread, vectorized) =================
__global__ void fill_kernel(const int* __restrict__ src,
                            const int* __restrict__ dst, int nE) {
    int q = blockIdx.x * blockDim.x + threadIdx.x;
    int base = q * 4;
    if (base + 4 <= nE) {
        int4 d = __ldg((const int4*)(dst + base));
        int4 s = __ldg((const int4*)(src + base));
        g_col[atomicAdd(&g_cnt2[d.x], 1)] = s.x;
        g_col[atomicAdd(&g_cnt2[d.y], 1)] = s.y;
        g_col[atomicAdd(&g_cnt2[d.z], 1)] = s.z;
        g_col[atomicAdd(&g_cnt2[d.w], 1)] = s.w;
    } else if (base < nE) {
        for (int i = base; i < nE; i++) {
            int d = __ldg(dst + i);
            g_col[atomicAdd(&g_cnt2[d], 1)] = __ldg(src + i);
        }
    }
}

// ================= gather-mean: warp per node =================
__global__ void gather_kernel(const float* __restrict__ feat, int n) {
    int gw = (int)(((size_t)blockIdx.x * blockDim.x + threadIdx.x) >> 5);
    int lane = threadIdx.x & 31;
    if (gw >= n) return;
    int end = __ldg(g_scanTmp + gw);
    int deg = __ldg(g_cnt + gw);
    int beg = end - deg;
    float4 acc = make_float4(0.f, 0.f, 0.f, 0.f);
    int i = beg;
    for (; i + 4 <= end; i += 4) {
        int s0 = __ldg(g_col + i);
        int s1 = __ldg(g_col + i + 1);
        int s2 = __ldg(g_col + i + 2);
        int s3 = __ldg(g_col + i + 3);
        float4 a = __ldg((const float4*)(feat + (size_t)s0 * FEAT) + lane);
        float4 b = __ldg((const float4*)(feat + (size_t)s1 * FEAT) + lane);
        float4 c = __ldg((const float4*)(feat + (size_t)s2 * FEAT) + lane);
        float4 d = __ldg((const float4*)(feat + (size_t)s3 * FEAT) + lane);
        acc.x += (a.x + b.x) + (c.x + d.x);
        acc.y += (a.y + b.y) + (c.y + d.y);
        acc.z += (a.z + b.z) + (c.z + d.z);
        acc.w += (a.w + b.w) + (c.w + d.w);
    }
    for (; i < end; i++) {
        int s0 = __ldg(g_col + i);
        float4 a = __ldg((const float4*)(feat + (size_t)s0 * FEAT) + lane);
        acc.x += a.x; acc.y += a.y; acc.z += a.z; acc.w += a.w;
    }
    float inv = 1.0f / (float)max(deg, 1);
    acc.x *= inv; acc.y *= inv; acc.z *= inv; acc.w *= inv;
    *((float4*)(g_msg + (size_t)gw * FEAT) + lane) = acc;
}

// ================= persistent pipelined SAGE GEMM (v5, byte-identical to R7) =================
__device__ __forceinline__ void fma2(u64& d, u64 a, u64 b) {
    asm("fma.rn.f32x2 %0, %1, %2, %0;" : "+l"(d) : "l"(a), "l"(b));
}
__device__ __forceinline__ u64 dup2(float x) {
    u64 r; asm("mov.b64 %0, {%1, %1};" : "=l"(r) : "f"(x)); return r;
}
__device__ __forceinline__ void unpack2(u64 v, float& lo, float& hi) {
    asm("mov.b64 {%0, %1}, %2;" : "=f"(lo), "=f"(hi) : "l"(v));
}

#define BR 128
#define SW_OFF  0                 // sW : [256][128] float = 128KB (Wself ‖ Wneigh)
#define SIN_OFF 131072            // sIn: [64][128] float  = 32KB (A chunk, k-major)
#define GEMM_SMEM_BYTES 163840

extern __shared__ char smc[];

__global__ __launch_bounds__(256, 1)
void sage_gemm_kernel(const float* __restrict__ X,
                      const float* __restrict__ Wself,
                      const float* __restrict__ Wneigh,
                      const float* __restrict__ bias,
                      float* __restrict__ OUT, int n, int nTiles, int ctrIdx) {
    float* sW  = (float*)(smc + SW_OFF);    // sW[k*128 + col], k = 0..255
    float* sIn = (float*)(smc + SIN_OFF);   // sIn[kl*128 + row], kl = 0..63
    __shared__ int s_tile;

    const int tid  = threadIdx.x;
    const int lane = tid & 31;
    const int wid  = tid >> 5;               // 0..7
    const int wr   = wid & 1;                // rows wr*64 .. +63
    const int wc   = wid >> 1;               // cols wc*32 .. +31
    const int lrow = lane >> 1;              // 0..15 -> rows wr*64 + lrow*4 .. +3
    const int lcol = lane & 1;               // cols wc*32 + lcol*16 .. +15
    const int colb = wc * 32 + lcol * 16;

    // ---- stage full W once: k<128 -> Wself[k], k>=128 -> Wneigh[k-128] ----
#pragma unroll
    for (int p = 0; p < 32; p++) {
        int idx = p * 256 + tid;             // float4 index, 0..8191
        int k   = idx >> 5;
        int c4  = (idx & 31) * 4;
        const float* wsrc = (k < 128) ? (Wself + (size_t)k * FEAT)
                                      : (Wneigh + (size_t)(k - 128) * FEAT);
        *(float4*)(sW + k * 128 + c4) = __ldg((const float4*)(wsrc + c4));
    }
    float bv[16];
#pragma unroll
    for (int q = 0; q < 16; q++) bv[q] = __ldg(bias + colb + q);
    __syncthreads();

    const int arow  = tid >> 1;              // staging row, 0..127
    const int akoff = (tid & 1) * 32;        // staging k half

    for (;;) {
        if (tid == 0) s_tile = atomicAdd(&g_ctr[ctrIdx], 1);
        __syncthreads();
        const int t = s_tile;
        __syncthreads();                     // allow s_tile reuse next iter
        if (t >= nTiles) break;
        const int row0 = t * BR;

        u64 acc[4][8];
#pragma unroll
        for (int i = 0; i < 4; i++)
#pragma unroll
            for (int j = 0; j < 8; j++) acc[i][j] = 0ull;

        // prefetch chunk 0 (X, k 0..63)
        float4 pf[8];
        {
            int grow = row0 + arow;
            bool ok = grow < n;
            const float4* ap = (const float4*)(X + (size_t)grow * FEAT + akoff);
#pragma unroll
            for (int j = 0; j < 8; j++)
                pf[j] = ok ? __ldg(ap + j) : make_float4(0.f, 0.f, 0.f, 0.f);
        }

        for (int ch = 0; ch < 4; ch++) {
            // ---- store prefetched chunk to sIn (transposed) ----
#pragma unroll
            for (int j = 0; j < 8; j++) {
                int kl = akoff + j * 4;
                sIn[(kl + 0) * 128 + arow] = pf[j].x;
                sIn[(kl + 1) * 128 + arow] = pf[j].y;
                sIn[(kl + 2) * 128 + arow] = pf[j].z;
                sIn[(kl + 3) * 128 + arow] = pf[j].w;
            }
            __syncthreads();

            // ---- prefetch next chunk ----
            if (ch < 3) {
                const float* srcp = (ch < 1) ? X : g_msg;   // (ch+1)<2 ? X : msg
                int koff = ((ch + 1) & 1) * 64;
                int grow = row0 + arow;
                bool ok = grow < n;
                const float4* ap = (const float4*)(srcp + (size_t)grow * FEAT + koff + akoff);
#pragma unroll
                for (int j = 0; j < 8; j++)
                    pf[j] = ok ? __ldg(ap + j) : make_float4(0.f, 0.f, 0.f, 0.f);
            }

            // ---- compute 64 k-steps ----
            const int wbase = ch * 64;
#pragma unroll 2
            for (int k = 0; k < 64; k++) {
                float4 av = *(const float4*)(sIn + k * 128 + wr * 64 + lrow * 4);
                u64 a0 = dup2(av.x), a1 = dup2(av.y), a2 = dup2(av.z), a3 = dup2(av.w);
                const u64* wq = (const u64*)(sW + (wbase + k) * 128 + colb);
                u64 w0 = wq[0], w1 = wq[1], w2 = wq[2], w3 = wq[3];
                u64 w4 = wq[4], w5 = wq[5], w6 = wq[6], w7 = wq[7];
                fma2(acc[0][0], a0, w0); fma2(acc[0][1], a0, w1); fma2(acc[0][2], a0, w2); fma2(acc[0][3], a0, w3);
                fma2(acc[0][4], a0, w4); fma2(acc[0][5], a0, w5); fma2(acc[0][6], a0, w6); fma2(acc[0][7], a0, w7);
                fma2(acc[1][0], a1, w0); fma2(acc[1][1], a1, w1); fma2(acc[1][2], a1, w2); fma2(acc[1][3], a1, w3);
                fma2(acc[1][4], a1, w4); fma2(acc[1][5], a1, w5); fma2(acc[1][6], a1, w6); fma2(acc[1][7], a1, w7);
                fma2(acc[2][0], a2, w0); fma2(acc[2][1], a2, w1); fma2(acc[2][2], a2, w2); fma2(acc[2][3], a2, w3);
                fma2(acc[2][4], a2, w4); fma2(acc[2][5], a2, w5); fma2(acc[2][6], a2, w6); fma2(acc[2][7], a2, w7);
                fma2(acc[3][0], a3, w0); fma2(acc[3][1], a3, w1); fma2(acc[3][2], a3, w2); fma2(acc[3][3], a3, w3);
                fma2(acc[3][4], a3, w4); fma2(acc[3][5], a3, w5); fma2(acc[3][6], a3, w6); fma2(acc[3][7], a3, w7);
            }
            __syncthreads();
        }

        // ---- epilogue: bias + relu + store ----
#pragma unroll
        for (int i = 0; i < 4; i++) {
            int grow = row0 + wr * 64 + lrow * 4 + i;
            if (grow >= n) continue;
            float o[16];
#pragma unroll
            for (int j = 0; j < 8; j++) unpack2(acc[i][j], o[2 * j], o[2 * j + 1]);
#pragma unroll
            for (int q = 0; q < 16; q++) o[q] = fmaxf(o[q] + bv[q], 0.0f);
            float4* dp = (float4*)(OUT + (size_t)grow * FEAT + colb);
            dp[0] = make_float4(o[0],  o[1],  o[2],  o[3]);
            dp[1] = make_float4(o[4],  o[5],  o[6],  o[7]);
            dp[2] = make_float4(o[8],  o[9],  o[10], o[11]);
            dp[3] = make_float4(o[12], o[13], o[14], o[15]);
        }
    }
}

// ================= final projection =================
__global__ void final_kernel(const float* __restrict__ Wf,
                             const float* __restrict__ bf,
                             float* __restrict__ out, int n) {
    int gw = (int)(((size_t)blockIdx.x * blockDim.x + threadIdx.x) >> 5);
    int lane = threadIdx.x & 31;
    if (gw >= n) return;
    float4 h = __ldg((const float4*)(g_h + (size_t)gw * FEAT) + lane);
    float s0 = 0.f, s1 = 0.f;
    const float* hv = (const float*)&h;
#pragma unroll
    for (int i = 0; i < 4; i++) {
        float2 w = __ldg((const float2*)Wf + lane * 4 + i);
        s0 += hv[i] * w.x;
        s1 += hv[i] * w.y;
    }
#pragma unroll
    for (int off = 16; off; off >>= 1) {
        s0 += __shfl_down_sync(0xffffffffu, s0, off);
        s1 += __shfl_down_sync(0xffffffffu, s1, off);
    }
    if (lane == 0) {
        out[2 * (size_t)gw]     = s0 + __ldg(bf);
        out[2 * (size_t)gw + 1] = s1 + __ldg(bf + 1);
    }
}

// ================= launch =================
extern "C" void kernel_launch(void* const* d_in, const int* in_sizes, int n_in,
                              void* d_out, int out_size) {
    const float* x   = (const float*)d_in[0];
    const float* Ws1 = (const float*)d_in[1];
    const float* Wn1 = (const float*)d_in[2];
    const float* b1  = (const float*)d_in[3];
    const float* Ws2 = (const float*)d_in[4];
    const float* Wn2 = (const float*)d_in[5];
    const float* b2  = (const float*)d_in[6];
    const float* Wf  = (const float*)d_in[7];
    const float* bf  = (const float*)d_in[8];
    const int*   src = (const int*)d_in[9];
    const int*   dst = (const int*)d_in[10];
    float* out = (float*)d_out;

    int n  = in_sizes[0] / FEAT;
    int nE = in_sizes[9];
    int nb = (n + 1023) / 1024;
    int nTiles = (n + BR - 1) / BR;
    int nQuads = (nE + 3) / 4;

    cudaFuncSetAttribute(sage_gemm_kernel,
                         cudaFuncAttributeMaxDynamicSharedMemorySize, GEMM_SMEM_BYTES);

    void* p_h = 0;
    cudaGetSymbolAddress(&p_h, g_h);
    float* h = (float*)p_h;

    // ---- CSR build ----
    zero_kernel<<<(n + 255) / 256, 256>>>(n, nb);
    hist_kernel<<<(nQuads + 255) / 256, 256>>>(dst, nE);
    scan_kernel<<<nb, 1024>>>(n);
    fill_kernel<<<(nQuads + 255) / 256, 256>>>(src, dst, nE);

    int gatherBlocks = (n + 7) / 8;

    // layer 1
    gather_kernel<<<gatherBlocks, 256>>>(x, n);
    sage_gemm_kernel<<<148, 256, GEMM_SMEM_BYTES>>>(x, Ws1, Wn1, b1, h, n, nTiles, 0);

    // layer 2
    gather_kernel<<<gatherBlocks, 256>>>(h, n);
    sage_gemm_kernel<<<148, 256, GEMM_SMEM_BYTES>>>(h, Ws2, Wn2, b2, h, n, nTiles, 1);

    // final projection
    final_kernel<<<(n + 7) / 8, 256>>>(Wf, bf, out, n);
}

// round 14
// speedup vs baseline: 1.0072x; 1.0072x over previous
#include <cuda_runtime.h>
#include <cstdint>

#define NN 100000
#define MAXE 1600000
#define FEAT 128
#define NB_MAX ((NN + 1023) / 1024)

typedef unsigned long long u64;

// ---------------- device scratch (no allocs allowed) ----------------
__device__ float g_msg[(size_t)NN * FEAT];
__device__ float g_h[(size_t)NN * FEAT];
__device__ int   g_cnt[NN];      // degree per node
__device__ int   g_cnt2[NN];     // fill cursor (scan writes exclusive prefix)
__device__ int   g_scanTmp[NN];  // inclusive prefix of cnt
__device__ int   g_col[MAXE];
__device__ u64   g_tile[NB_MAX]; // lookback tile state: flag<<32 | value
__device__ int   g_ctr[4];       // GEMM tile counters per layer

#define FLAG_PARTIAL 1ULL
#define FLAG_INCL    2ULL

// ================= zero =================
__global__ void zero_kernel(int n, int nb) {
    int i = blockIdx.x * blockDim.x + threadIdx.x;
    if (i < n) g_cnt[i] = 0;
    if (i < nb) g_tile[i] = 0;
    if (i < 4) g_ctr[i] = 0;
}

// ================= histogram =================
__global__ void hist_kernel(const int* __restrict__ dst, int nE) {
    int i = blockIdx.x * blockDim.x + threadIdx.x;
    if (i < nE) atomicAdd(&g_cnt[__ldg(dst + i)], 1);
}

// ================= single-pass scan (decoupled lookback) =================
// writes inclusive prefix to g_scanTmp AND exclusive prefix to g_cnt2 (fill cursor)
__global__ __launch_bounds__(1024)
void scan_kernel(int n) {
    __shared__ int sh[1024];
    __shared__ int s_prefix;
    const int b = blockIdx.x;
    const int t = threadIdx.x;
    const int i = b * 1024 + t;

    int v = (i < n) ? g_cnt[i] : 0;
    sh[t] = v;
    __syncthreads();
#pragma unroll
    for (int off = 1; off < 1024; off <<= 1) {
        int tv = (t >= off) ? sh[t - off] : 0;
        __syncthreads();
        sh[t] += tv;
        __syncthreads();
    }
    int total = sh[1023];

    if (b == 0) {
        if (t == 0) {
            s_prefix = 0;
            atomicExch(&g_tile[0], (FLAG_INCL << 32) | (unsigned)total);
        }
    } else {
        if (t == 0)
            atomicExch(&g_tile[b], (FLAG_PARTIAL << 32) | (unsigned)total);
        if (t < 32) {
            int lane = t;
            int offset = b - 1;
            int prefix = 0;
            for (;;) {
                int idx = offset - lane;
                u64 st = (idx >= 0) ? atomicAdd(&g_tile[idx], 0ULL)
                                    : (FLAG_INCL << 32);
                unsigned rdy = __ballot_sync(0xffffffffu, (st >> 32) != 0);
                if (rdy != 0xffffffffu) continue;
                unsigned inclm = __ballot_sync(0xffffffffu, (st >> 32) == FLAG_INCL);
                int val = (int)(unsigned)st;
                if (inclm) {
                    int L = __ffs(inclm) - 1;
                    int c = (lane <= L) ? val : 0;
#pragma unroll
                    for (int o = 16; o; o >>= 1) c += __shfl_xor_sync(0xffffffffu, c, o);
                    prefix += c;
                    break;
                } else {
                    int c = val;
#pragma unroll
                    for (int o = 16; o; o >>= 1) c += __shfl_xor_sync(0xffffffffu, c, o);
                    prefix += c;
                    offset -= 32;
                }
            }
            if (lane == 0) {
                s_prefix = prefix;
                atomicExch(&g_tile[b], (FLAG_INCL << 32) | (unsigned)(prefix + total));
            }
        }
    }
    __syncthreads();
    if (i < n) {
        int incl = sh[t] + s_prefix;
        g_scanTmp[i] = incl;
        g_cnt2[i]    = incl - v;   // exclusive prefix = fill cursor base
    }
}

// ================= fill CSR columns (single atomic, no extra loads) =================
__global__ void fill_kernel(const int* __restrict__ src,
                            const int* __restrict__ dst, int nE) {
    int i = blockIdx.x * blockDim.x + threadIdx.x;
    if (i >= nE) return;
    int d = __ldg(dst + i);
    int pos = atomicAdd(&g_cnt2[d], 1);
    g_col[pos] = __ldg(src + i);
}

// ================= gather-mean: warp per node =================
__global__ void gather_kernel(const float* __restrict__ feat, int n) {
    int gw = (int)(((size_t)blockIdx.x * blockDim.x + threadIdx.x) >> 5);
    int lane = threadIdx.x & 31;
    if (gw >= n) return;
    int end = __ldg(g_scanTmp + gw);
    int deg = __ldg(g_cnt + gw);
    int beg = end - deg;
    float4 acc = make_float4(0.f, 0.f, 0.f, 0.f);
    int i = beg;
    for (; i + 4 <= end; i += 4) {
        int s0 = __ldg(g_col + i);
        int s1 = __ldg(g_col + i + 1);
        int s2 = __ldg(g_col + i + 2);
        int s3 = __ldg(g_col + i + 3);
        float4 a = __ldg((const float4*)(feat + (size_t)s0 * FEAT) + lane);
        float4 b = __ldg((const float4*)(feat + (size_t)s1 * FEAT) + lane);
        float4 c = __ldg((const float4*)(feat + (size_t)s2 * FEAT) + lane);
        float4 d = __ldg((const float4*)(feat + (size_t)s3 * FEAT) + lane);
        acc.x += (a.x + b.x) + (c.x + d.x);
        acc.y += (a.y + b.y) + (c.y + d.y);
        acc.z += (a.z + b.z) + (c.z + d.z);
        acc.w += (a.w + b.w) + (c.w + d.w);
    }
    for (; i < end; i++) {
        int s0 = __ldg(g_col + i);
        float4 a = __ldg((const float4*)(feat + (size_t)s0 * FEAT) + lane);
        acc.x += a.x; acc.y += a.y; acc.z += a.z; acc.w += a.w;
    }
    float inv = 1.0f / (float)max(deg, 1);
    acc.x *= inv; acc.y *= inv; acc.z *= inv; acc.w *= inv;
    *((float4*)(g_msg + (size_t)gw * FEAT) + lane) = acc;
}

// ================= persistent pipelined SAGE GEMM (v5, locked) =================
__device__ __forceinline__ void fma2(u64& d, u64 a, u64 b) {
    asm("fma.rn.f32x2 %0, %1, %2, %0;" : "+l"(d) : "l"(a), "l"(b));
}
__device__ __forceinline__ u64 dup2(float x) {
    u64 r; asm("mov.b64 %0, {%1, %1};" : "=l"(r) : "f"(x)); return r;
}
__device__ __forceinline__ void unpack2(u64 v, float& lo, float& hi) {
    asm("mov.b64 {%0, %1}, %2;" : "=f"(lo), "=f"(hi) : "l"(v));
}

#define BR 128
#define SW_OFF  0                 // sW : [256][128] float = 128KB (Wself ‖ Wneigh)
#define SIN_OFF 131072            // sIn: [64][128] float  = 32KB (A chunk, k-major)
#define GEMM_SMEM_BYTES 163840

extern __shared__ char smc[];

__global__ __launch_bounds__(256, 1)
void sage_gemm_kernel(const float* __restrict__ X,
                      const float* __restrict__ Wself,
                      const float* __restrict__ Wneigh,
                      const float* __restrict__ bias,
                      float* __restrict__ OUT, int n, int nTiles, int ctrIdx) {
    float* sW  = (float*)(smc + SW_OFF);    // sW[k*128 + col], k = 0..255
    float* sIn = (float*)(smc + SIN_OFF);   // sIn[kl*128 + row], kl = 0..63
    __shared__ int s_tile;

    const int tid  = threadIdx.x;
    const int lane = tid & 31;
    const int wid  = tid >> 5;               // 0..7
    const int wr   = wid & 1;                // rows wr*64 .. +63
    const int wc   = wid >> 1;               // cols wc*32 .. +31
    const int lrow = lane >> 1;              // 0..15 -> rows wr*64 + lrow*4 .. +3
    const int lcol = lane & 1;               // cols wc*32 + lcol*16 .. +15
    const int colb = wc * 32 + lcol * 16;

    // ---- stage full W once: k<128 -> Wself[k], k>=128 -> Wneigh[k-128] ----
#pragma unroll
    for (int p = 0; p < 32; p++) {
        int idx = p * 256 + tid;             // float4 index, 0..8191
        int k   = idx >> 5;
        int c4  = (idx & 31) * 4;
        const float* wsrc = (k < 128) ? (Wself + (size_t)k * FEAT)
                                      : (Wneigh + (size_t)(k - 128) * FEAT);
        *(float4*)(sW + k * 128 + c4) = __ldg((const float4*)(wsrc + c4));
    }
    float bv[16];
#pragma unroll
    for (int q = 0; q < 16; q++) bv[q] = __ldg(bias + colb + q);
    __syncthreads();

    const int arow  = tid >> 1;              // staging row, 0..127
    const int akoff = (tid & 1) * 32;        // staging k half

    for (;;) {
        if (tid == 0) s_tile = atomicAdd(&g_ctr[ctrIdx], 1);
        __syncthreads();
        const int t = s_tile;
        __syncthreads();                     // allow s_tile reuse next iter
        if (t >= nTiles) break;
        const int row0 = t * BR;

        u64 acc[4][8];
#pragma unroll
        for (int i = 0; i < 4; i++)
#pragma unroll
            for (int j = 0; j < 8; j++) acc[i][j] = 0ull;

        // prefetch chunk 0 (X, k 0..63)
        float4 pf[8];
        {
            int grow = row0 + arow;
            bool ok = grow < n;
            const float4* ap = (const float4*)(X + (size_t)grow * FEAT + akoff);
#pragma unroll
            for (int j = 0; j < 8; j++)
                pf[j] = ok ? __ldg(ap + j) : make_float4(0.f, 0.f, 0.f, 0.f);
        }

        for (int ch = 0; ch < 4; ch++) {
            // ---- store prefetched chunk to sIn (transposed) ----
#pragma unroll
            for (int j = 0; j < 8; j++) {
                int kl = akoff + j * 4;
                sIn[(kl + 0) * 128 + arow] = pf[j].x;
                sIn[(kl + 1) * 128 + arow] = pf[j].y;
                sIn[(kl + 2) * 128 + arow] = pf[j].z;
                sIn[(kl + 3) * 128 + arow] = pf[j].w;
            }
            __syncthreads();

            // ---- prefetch next chunk ----
            if (ch < 3) {
                const float* srcp = (ch < 1) ? X : g_msg;   // (ch+1)<2 ? X : msg
                int koff = ((ch + 1) & 1) * 64;
                int grow = row0 + arow;
                bool ok = grow < n;
                const float4* ap = (const float4*)(srcp + (size_t)grow * FEAT + koff + akoff);
#pragma unroll
                for (int j = 0; j < 8; j++)
                    pf[j] = ok ? __ldg(ap + j) : make_float4(0.f, 0.f, 0.f, 0.f);
            }

            // ---- compute 64 k-steps ----
            const int wbase = ch * 64;
#pragma unroll 2
            for (int k = 0; k < 64; k++) {
                float4 av = *(const float4*)(sIn + k * 128 + wr * 64 + lrow * 4);
                u64 a0 = dup2(av.x), a1 = dup2(av.y), a2 = dup2(av.z), a3 = dup2(av.w);
                const u64* wq = (const u64*)(sW + (wbase + k) * 128 + colb);
                u64 w0 = wq[0], w1 = wq[1], w2 = wq[2], w3 = wq[3];
                u64 w4 = wq[4], w5 = wq[5], w6 = wq[6], w7 = wq[7];
                fma2(acc[0][0], a0, w0); fma2(acc[0][1], a0, w1); fma2(acc[0][2], a0, w2); fma2(acc[0][3], a0, w3);
                fma2(acc[0][4], a0, w4); fma2(acc[0][5], a0, w5); fma2(acc[0][6], a0, w6); fma2(acc[0][7], a0, w7);
                fma2(acc[1][0], a1, w0); fma2(acc[1][1], a1, w1); fma2(acc[1][2], a1, w2); fma2(acc[1][3], a1, w3);
                fma2(acc[1][4], a1, w4); fma2(acc[1][5], a1, w5); fma2(acc[1][6], a1, w6); fma2(acc[1][7], a1, w7);
                fma2(acc[2][0], a2, w0); fma2(acc[2][1], a2, w1); fma2(acc[2][2], a2, w2); fma2(acc[2][3], a2, w3);
                fma2(acc[2][4], a2, w4); fma2(acc[2][5], a2, w5); fma2(acc[2][6], a2, w6); fma2(acc[2][7], a2, w7);
                fma2(acc[3][0], a3, w0); fma2(acc[3][1], a3, w1); fma2(acc[3][2], a3, w2); fma2(acc[3][3], a3, w3);
                fma2(acc[3][4], a3, w4); fma2(acc[3][5], a3, w5); fma2(acc[3][6], a3, w6); fma2(acc[3][7], a3, w7);
            }
            __syncthreads();
        }

        // ---- epilogue: bias + relu + store ----
#pragma unroll
        for (int i = 0; i < 4; i++) {
            int grow = row0 + wr * 64 + lrow * 4 + i;
            if (grow >= n) continue;
            float o[16];
#pragma unroll
            for (int j = 0; j < 8; j++) unpack2(acc[i][j], o[2 * j], o[2 * j + 1]);
#pragma unroll
            for (int q = 0; q < 16; q++) o[q] = fmaxf(o[q] + bv[q], 0.0f);
            float4* dp = (float4*)(OUT + (size_t)grow * FEAT + colb);
            dp[0] = make_float4(o[0],  o[1],  o[2],  o[3]);
            dp[1] = make_float4(o[4],  o[5],  o[6],  o[7]);
            dp[2] = make_float4(o[8],  o[9],  o[10], o[11]);
            dp[3] = make_float4(o[12], o[13], o[14], o[15]);
        }
    }
}

// ================= final projection =================
__global__ void final_kernel(const float* __restrict__ Wf,
                             const float* __restrict__ bf,
                             float* __restrict__ out, int n) {
    int gw = (int)(((size_t)blockIdx.x * blockDim.x + threadIdx.x) >> 5);
    int lane = threadIdx.x & 31;
    if (gw >= n) return;
    float4 h = __ldg((const float4*)(g_h + (size_t)gw * FEAT) + lane);
    float s0 = 0.f, s1 = 0.f;
    const float* hv = (const float*)&h;
#pragma unroll
    for (int i = 0; i < 4; i++) {
        float2 w = __ldg((const float2*)Wf + lane * 4 + i);
        s0 += hv[i] * w.x;
        s1 += hv[i] * w.y;
    }
#pragma unroll
    for (int off = 16; off; off >>= 1) {
        s0 += __shfl_down_sync(0xffffffffu, s0, off);
        s1 += __shfl_down_sync(0xffffffffu, s1, off);
    }
    if (lane == 0) {
        out[2 * (size_t)gw]     = s0 + __ldg(bf);
        out[2 * (size_t)gw + 1] = s1 + __ldg(bf + 1);
    }
}

// ================= launch =================
extern "C" void kernel_launch(void* const* d_in, const int* in_sizes, int n_in,
                              void* d_out, int out_size) {
    const float* x   = (const float*)d_in[0];
    const float* Ws1 = (const float*)d_in[1];
    const float* Wn1 = (const float*)d_in[2];
    const float* b1  = (const float*)d_in[3];
    const float* Ws2 = (const float*)d_in[4];
    const float* Wn2 = (const float*)d_in[5];
    const float* b2  = (const float*)d_in[6];
    const float* Wf  = (const float*)d_in[7];
    const float* bf  = (const float*)d_in[8];
    const int*   src = (const int*)d_in[9];
    const int*   dst = (const int*)d_in[10];
    float* out = (float*)d_out;

    int n  = in_sizes[0] / FEAT;
    int nE = in_sizes[9];
    int nb = (n + 1023) / 1024;
    int nTiles = (n + BR - 1) / BR;

    cudaFuncSetAttribute(sage_gemm_kernel,
                         cudaFuncAttributeMaxDynamicSharedMemorySize, GEMM_SMEM_BYTES);

    void* p_h = 0;
    cudaGetSymbolAddress(&p_h, g_h);
    float* h = (float*)p_h;

    // ---- CSR build ----
    zero_kernel<<<(n + 255) / 256, 256>>>(n, nb);
    hist_kernel<<<(nE + 255) / 256, 256>>>(dst, nE);
    scan_kernel<<<nb, 1024>>>(n);
    fill_kernel<<<(nE + 255) / 256, 256>>>(src, dst, nE);

    int gatherBlocks = (n + 7) / 8;

    // layer 1
    gather_kernel<<<gatherBlocks, 256>>>(x, n);
    sage_gemm_kernel<<<148, 256, GEMM_SMEM_BYTES>>>(x, Ws1, Wn1, b1, h, n, nTiles, 0);

    // layer 2
    gather_kernel<<<gatherBlocks, 256>>>(h, n);
    sage_gemm_kernel<<<148, 256, GEMM_SMEM_BYTES>>>(h, Ws2, Wn2, b2, h, n, nTiles, 1);

    // final projection
    final_kernel<<<(n + 7) / 8, 256>>>(Wf, bf, out, n);
}